// round 5
// baseline (speedup 1.0000x reference)
#include <cuda_runtime.h>

// Problem constants
#define B   16
#define C   16
#define H   256
#define W   256
#define F   32
#define TY  32      // output tile rows per block
#define TX  64      // output tile cols per block
#define FG  8       // filters per block
#define IPITCH 68   // shared input row pitch (floats, 16B-aligned rows)
#define IROWS 34
#define ICOLS 66    // valid cols stored (cols 66,67 of pitch unused garbage)
#define NLD 9       // ceil(34*66/256)

typedef unsigned long long ull;

// packed f32x2 FMA (SASS FFMA2)
__device__ __forceinline__ void fma2(ull& d, ull a, ull b) {
    asm("fma.rn.f32x2 %0, %1, %2, %0;" : "+l"(d) : "l"(a), "l"(b));
}
__device__ __forceinline__ ull pack2(float lo, float hi) {
    ull p;
    asm("mov.b64 %0, {%1, %2};" : "=l"(p) : "f"(lo), "f"(hi));
    return p;
}
__device__ __forceinline__ void unpack2(ull p, float& lo, float& hi) {
    asm("mov.b64 {%0, %1}, %2;" : "=f"(lo), "=f"(hi) : "l"(p));
}

__global__ __launch_bounds__(256)
void conv3x3_sig_kernel(const float* __restrict__ x,
                        const float* __restrict__ weights,
                        const float* __restrict__ biases,
                        float* __restrict__ out) {
    // grid: (W/TX, H/TY, B * (F/FG)) = (4, 8, 64)
    const int tx = blockIdx.x;
    const int ty = blockIdx.y;
    const int b  = blockIdx.z >> 2;
    const int g  = blockIdx.z & 3;

    const int tid = threadIdx.x;        // 0..255
    const int row = tid >> 3;           // 0..31 output row within tile
    const int cg8 = (tid & 7) * 8;      // output col offset (8 px/thread)

    __shared__ __align__(16) float s_in[2][IROWS * IPITCH];
    __shared__ __align__(16) float4 s_w4[C * 9 * (FG / 2)]; // (w0,w0,w1,w1) per 2 filters

    // ---- stage weights: layout [(c*9 + tap)*32 + f] ----
    for (int i = tid; i < C * 9 * (FG / 2); i += 256) {
        const int c   = i / 36;
        const int rem = i - c * 36;
        const int tap = rem >> 2;
        const int fp  = rem & 3;
        const float w0 = weights[(c * 9 + tap) * F + g * FG + 2 * fp + 0];
        const float w1 = weights[(c * 9 + tap) * F + g * FG + 2 * fp + 1];
        s_w4[i] = make_float4(w0, w0, w1, w1);
    }

    const int y0 = ty * TY - 1;         // input tile origin (with pad)
    const int x0 = tx * TX - 1;

    // ---- precompute tile-load geometry (channel-invariant) ----
    int  goff[NLD];
    int  sdst[NLD];
    bool ldp[NLD];
    #pragma unroll
    for (int i = 0; i < NLD; i++) {
        const int idx = tid + 256 * i;
        const bool slot = (idx < IROWS * ICOLS);
        const int r  = idx / ICOLS;
        const int cc = idx - r * ICOLS;
        const int gy = y0 + r;
        const int gxx = x0 + cc;
        ldp[i]  = slot && ((unsigned)gy < (unsigned)H) && ((unsigned)gxx < (unsigned)W);
        goff[i] = gy * W + gxx;
        sdst[i] = slot ? (r * IPITCH + cc) : -1;
    }

    const float* gx0 = x + ((size_t)b * C) * H * W;

    // accumulators: 8 filters x 4 f32x2 pairs (pixels {0,1}{2,3}{4,5}{6,7})
    ull acc[FG * 4];
    #pragma unroll
    for (int i = 0; i < FG * 4; i++) acc[i] = 0ull;

    // ---- prologue: channel 0 -> buffer 0 ----
    {
        float v[NLD];
        #pragma unroll
        for (int i = 0; i < NLD; i++) v[i] = ldp[i] ? gx0[goff[i]] : 0.f;
        #pragma unroll
        for (int i = 0; i < NLD; i++) if (sdst[i] >= 0) s_in[0][sdst[i]] = v[i];
    }
    __syncthreads();

    for (int c = 0; c < C; c++) {
        const int cur = c & 1;

        // ---- issue next channel's loads (latency overlapped with compute) ----
        float nv[NLD];
        if (c + 1 < C) {
            const float* gn = gx0 + (size_t)(c + 1) * H * W;
            #pragma unroll
            for (int i = 0; i < NLD; i++) nv[i] = ldp[i] ? gn[goff[i]] : 0.f;
        }

        // ---- compute channel c ----
        const ulonglong2* wrow =
            reinterpret_cast<const ulonglong2*>(&s_w4[c * 36]);

        #pragma unroll
        for (int kh = 0; kh < 3; kh++) {
            const float* base = &s_in[cur][(row + kh) * IPITCH + cg8];
            const float4 a  = *reinterpret_cast<const float4*>(base);      // v0..v3
            const float4 bq = *reinterpret_cast<const float4*>(base + 4);  // v4..v7
            const float4 cq = *reinterpret_cast<const float4*>(base + 8);  // v8..v11

            // even pairs: free register-pair aliasing
            const ull e0 = pack2(a.x, a.y);
            const ull e1 = pack2(a.z, a.w);
            const ull e2 = pack2(bq.x, bq.y);
            const ull e3 = pack2(bq.z, bq.w);
            const ull e4 = pack2(cq.x, cq.y);
            // odd pairs: real packs
            const ull o0 = pack2(a.y, a.z);
            const ull o1 = pack2(a.w, bq.x);
            const ull o2 = pack2(bq.y, bq.z);
            const ull o3 = pack2(bq.w, cq.x);

            const ull P[3][4] = {
                { e0, e1, e2, e3 },   // kw=0
                { o0, o1, o2, o3 },   // kw=1
                { e1, e2, e3, e4 }    // kw=2
            };

            #pragma unroll
            for (int kw = 0; kw < 3; kw++) {
                #pragma unroll
                for (int fp = 0; fp < 4; fp++) {
                    const ulonglong2 wv = wrow[(kh * 3 + kw) * 4 + fp]; // LDS.128 bcast
                    #pragma unroll
                    for (int q = 0; q < 4; q++) {
                        fma2(acc[(fp * 2 + 0) * 4 + q], P[kw][q], wv.x);
                        fma2(acc[(fp * 2 + 1) * 4 + q], P[kw][q], wv.y);
                    }
                }
            }
        }

        // ---- store next channel into other buffer ----
        if (c + 1 < C) {
            #pragma unroll
            for (int i = 0; i < NLD; i++)
                if (sdst[i] >= 0) s_in[1 - cur][sdst[i]] = nv[i];
        }
        __syncthreads();
    }

    // ---- epilogue: bias + sigmoid + store ----
    const int oy = ty * TY + row;
    const int ox = tx * TX + cg8;
    #pragma unroll
    for (int f = 0; f < FG; f++) {
        const int fo = g * FG + f;
        float r[8];
        #pragma unroll
        for (int q = 0; q < 4; q++)
            unpack2(acc[f * 4 + q], r[2 * q], r[2 * q + 1]);

        const float4 b0 = *reinterpret_cast<const float4*>(
            &biases[((size_t)fo * H + oy) * W + ox]);
        const float4 b1 = *reinterpret_cast<const float4*>(
            &biases[((size_t)fo * H + oy) * W + ox + 4]);
        r[0] += b0.x; r[1] += b0.y; r[2] += b0.z; r[3] += b0.w;
        r[4] += b1.x; r[5] += b1.y; r[6] += b1.z; r[7] += b1.w;

        float4 o0, o1;
        o0.x = 1.f / (1.f + __expf(-r[0]));
        o0.y = 1.f / (1.f + __expf(-r[1]));
        o0.z = 1.f / (1.f + __expf(-r[2]));
        o0.w = 1.f / (1.f + __expf(-r[3]));
        o1.x = 1.f / (1.f + __expf(-r[4]));
        o1.y = 1.f / (1.f + __expf(-r[5]));
        o1.z = 1.f / (1.f + __expf(-r[6]));
        o1.w = 1.f / (1.f + __expf(-r[7]));

        float* op = &out[(((size_t)b * F + fo) * H + oy) * W + ox];
        *reinterpret_cast<float4*>(op)     = o0;
        *reinterpret_cast<float4*>(op + 4) = o1;
    }
}

extern "C" void kernel_launch(void* const* d_in, const int* in_sizes, int n_in,
                              void* d_out, int out_size) {
    const float* x       = (const float*)d_in[0];
    const float* weights = (const float*)d_in[1];
    const float* biases  = (const float*)d_in[2];
    float* out = (float*)d_out;

    dim3 grid(W / TX, H / TY, B * (F / FG));   // (4, 8, 64)
    dim3 block(256);
    conv3x3_sig_kernel<<<grid, block>>>(x, weights, biases, out);
}

// round 6
// speedup vs baseline: 1.4705x; 1.4705x over previous
#include <cuda_runtime.h>

// Problem constants
#define B   16
#define C   16
#define H   256
#define W   256
#define F   32
#define TILE 32     // output tile 32x32
#define FG  8       // filters per block
#define SPITCH 36   // shared input row pitch (multiple of 4 -> 16B-aligned rows)

typedef unsigned long long ull;

// packed f32x2 FMA (SASS FFMA2)
__device__ __forceinline__ void fma2(ull& d, ull a, ull b) {
    asm("fma.rn.f32x2 %0, %1, %2, %0;" : "+l"(d) : "l"(a), "l"(b));
}
__device__ __forceinline__ ull pack2(float lo, float hi) {
    ull p;
    asm("mov.b64 %0, {%1, %2};" : "=l"(p) : "f"(lo), "f"(hi));
    return p;
}
__device__ __forceinline__ void unpack2(ull p, float& lo, float& hi) {
    asm("mov.b64 {%0, %1}, %2;" : "=f"(lo), "=f"(hi) : "l"(p));
}

__global__ __launch_bounds__(256, 3)
void conv3x3_sig_kernel(const float* __restrict__ x,
                        const float* __restrict__ weights,
                        const float* __restrict__ biases,
                        float* __restrict__ out) {
    // grid: (W/TILE, H/TILE, B * (F/FG)) = (8, 8, 64)
    const int tx = blockIdx.x;
    const int ty = blockIdx.y;
    const int b  = blockIdx.z >> 2;
    const int g  = blockIdx.z & 3;

    const int tid = threadIdx.x;        // 0..255
    const int row = tid >> 3;           // 0..31 output row within tile
    const int c0  = (tid & 7) * 4;      // output col offset (4 px/thread)

    __shared__ __align__(16) float  s_in[2][34 * SPITCH];
    __shared__ __align__(16) float4 s_w4[C * 9 * (FG / 2)];  // (w0,w0,w1,w1)

    // ---- stage weights: src layout [(c*9 + tap)*32 + f] ----
    for (int i = tid; i < C * 9 * (FG / 2); i += 256) {
        const int c   = i / 36;
        const int rem = i - c * 36;
        const int tap = rem >> 2;       // 0..8
        const int fp  = rem & 3;        // filter pair 0..3
        const float w0 = weights[(c * 9 + tap) * F + g * FG + 2 * fp + 0];
        const float w1 = weights[(c * 9 + tap) * F + g * FG + 2 * fp + 1];
        s_w4[i] = make_float4(w0, w0, w1, w1);
    }

    const int y0 = ty * TILE - 1;
    const int x0 = tx * TILE - 1;

    // ---- precompute tile-load geometry (channel-invariant) ----
    // 34 rows x 34 cols valid; 5 loads of 256 threads cover 34*34=1156
    int  goff[5];
    int  sdst[5];
    bool ldp[5];
    #pragma unroll
    for (int i = 0; i < 5; i++) {
        const int idx = tid + 256 * i;
        const bool slot = (idx < 34 * 34);
        const int r  = idx / 34;
        const int cc = idx - r * 34;
        const int gy = y0 + r;
        const int gxx = x0 + cc;
        ldp[i]  = slot && ((unsigned)gy < (unsigned)H) && ((unsigned)gxx < (unsigned)W);
        goff[i] = gy * W + gxx;
        sdst[i] = slot ? (r * SPITCH + cc) : -1;
    }

    const float* gx0 = x + ((size_t)b * C) * H * W;

    // accumulators: 8 filters x 2 f32x2 pairs
    ull acc[FG * 2];
    #pragma unroll
    for (int i = 0; i < FG * 2; i++) acc[i] = 0ull;

    // ---- prologue: channel 0 -> buffer 0 ----
    {
        float v[5];
        #pragma unroll
        for (int i = 0; i < 5; i++) v[i] = ldp[i] ? gx0[goff[i]] : 0.f;
        #pragma unroll
        for (int i = 0; i < 5; i++) if (sdst[i] >= 0) s_in[0][sdst[i]] = v[i];
    }
    __syncthreads();

    for (int c = 0; c < C; c++) {
        const int cur = c & 1;

        // ---- issue next channel's loads early ----
        float nv[5];
        if (c + 1 < C) {
            const float* gn = gx0 + (size_t)(c + 1) * H * W;
            #pragma unroll
            for (int i = 0; i < 5; i++) nv[i] = ldp[i] ? gn[goff[i]] : 0.f;
        }

        // ---- compute channel c ----
        const ulonglong2* wc =
            reinterpret_cast<const ulonglong2*>(&s_w4[c * 36]);

        #pragma unroll
        for (int kh = 0; kh < 3; kh++) {
            const float* base = &s_in[cur][(row + kh) * SPITCH + c0];
            const float4 a = *reinterpret_cast<const float4*>(base);      // v0..v3
            const float2 d = *reinterpret_cast<const float2*>(base + 4);  // v4,v5

            // even pairs alias aligned register pairs (free); odd pairs packed
            const ull e0 = pack2(a.x, a.y);
            const ull e1 = pack2(a.z, a.w);
            const ull e2 = pack2(d.x, d.y);
            const ull o0 = pack2(a.y, a.z);
            const ull o1 = pack2(a.w, d.x);

            const ull pa[3] = { e0, o0, e1 };   // pixels {0,1}, kw=0..2
            const ull pb[3] = { e1, o1, e2 };   // pixels {2,3}, kw=0..2

            #pragma unroll
            for (int kw = 0; kw < 3; kw++) {
                #pragma unroll
                for (int fp = 0; fp < 4; fp++) {
                    const ulonglong2 wv = wc[(kh * 3 + kw) * 4 + fp]; // LDS.128 bcast
                    fma2(acc[(2 * fp + 0) * 2 + 0], pa[kw], wv.x);
                    fma2(acc[(2 * fp + 0) * 2 + 1], pb[kw], wv.x);
                    fma2(acc[(2 * fp + 1) * 2 + 0], pa[kw], wv.y);
                    fma2(acc[(2 * fp + 1) * 2 + 1], pb[kw], wv.y);
                }
            }
        }

        // ---- store next channel into other buffer ----
        if (c + 1 < C) {
            #pragma unroll
            for (int i = 0; i < 5; i++)
                if (sdst[i] >= 0) s_in[1 - cur][sdst[i]] = nv[i];
        }
        __syncthreads();
    }

    // ---- epilogue: bias + sigmoid + store ----
    const int oy = ty * TILE + row;
    const int ox = tx * TILE + c0;
    #pragma unroll
    for (int f = 0; f < FG; f++) {
        const int fo = g * FG + f;
        float r0, r1, r2, r3;
        unpack2(acc[f * 2 + 0], r0, r1);
        unpack2(acc[f * 2 + 1], r2, r3);

        const float4 bb = *reinterpret_cast<const float4*>(
            &biases[((size_t)fo * H + oy) * W + ox]);
        r0 += bb.x; r1 += bb.y; r2 += bb.z; r3 += bb.w;

        float4 o;
        o.x = 1.f / (1.f + __expf(-r0));
        o.y = 1.f / (1.f + __expf(-r1));
        o.z = 1.f / (1.f + __expf(-r2));
        o.w = 1.f / (1.f + __expf(-r3));

        *reinterpret_cast<float4*>(
            &out[(((size_t)b * F + fo) * H + oy) * W + ox]) = o;
    }
}

extern "C" void kernel_launch(void* const* d_in, const int* in_sizes, int n_in,
                              void* d_out, int out_size) {
    const float* x       = (const float*)d_in[0];
    const float* weights = (const float*)d_in[1];
    const float* biases  = (const float*)d_in[2];
    float* out = (float*)d_out;

    dim3 grid(W / TILE, H / TILE, B * (F / FG));   // (8, 8, 64)
    dim3 block(256);
    conv3x3_sig_kernel<<<grid, block>>>(x, weights, biases, out);
}

// round 8
// speedup vs baseline: 2.2987x; 1.5631x over previous
#include <cuda_runtime.h>
#include <cuda_bf16.h>
#include <stdint.h>

// ---------------- problem constants ----------------
#define Bs 16
#define Cs 16
#define Hs 256
#define Ws 256
#define Fs 32

#define MPX 128                 // output px per block (half an image row)
#define PITCH 132               // staged px slots per kh row (130 used)
#define APLANE (3 * PITCH * 32) // bytes per A precision plane (32B/px) = 12672
#define BPLANE (9 * 32 * 32)    // bytes per B precision plane = 9216
#define SMEM_SZ (2 * APLANE + 2 * BPLANE)   // 43776 B

__device__ __forceinline__ uint32_t smem_u32(const void* p) {
    uint32_t a;
    asm("{ .reg .u64 t; cvta.to.shared.u64 t, %1; cvt.u32.u64 %0, t; }"
        : "=r"(a) : "l"(p));
    return a;
}
__device__ __forceinline__ uint32_t pk2(__nv_bfloat16 a, __nv_bfloat16 b) {
    union { __nv_bfloat162 v; uint32_t u; } cv;
    cv.v = __nv_bfloat162(a, b);   // low half = a (even index)
    return cv.u;
}
__device__ __forceinline__ void ldmA(uint32_t addr, uint32_t* a) {
    asm volatile("ldmatrix.sync.aligned.m8n8.x4.shared.b16 {%0,%1,%2,%3}, [%4];"
                 : "=r"(a[0]), "=r"(a[1]), "=r"(a[2]), "=r"(a[3]) : "r"(addr));
}
__device__ __forceinline__ void mma16816(float* d, const uint32_t* a,
                                         uint32_t b0, uint32_t b1) {
    asm volatile(
        "mma.sync.aligned.m16n8k16.row.col.f32.bf16.bf16.f32 "
        "{%0,%1,%2,%3}, {%4,%5,%6,%7}, {%8,%9}, {%0,%1,%2,%3};"
        : "+f"(d[0]), "+f"(d[1]), "+f"(d[2]), "+f"(d[3])
        : "r"(a[0]), "r"(a[1]), "r"(a[2]), "r"(a[3]), "r"(b0), "r"(b1));
}

__global__ __launch_bounds__(128, 4)
void conv_hmma_kernel(const float* __restrict__ x,
                      const float* __restrict__ weights,
                      const float* __restrict__ biases,
                      float* __restrict__ out) {
    __shared__ __align__(128) char smem[SMEM_SZ];
    const uint32_t sb = smem_u32(smem);

    const int tid  = threadIdx.x;
    const int warp = tid >> 5;
    const int lane = tid & 31;

    const int x0 = blockIdx.x * MPX;     // 0 or 128
    const int r  = blockIdx.y;           // output row
    const int b  = blockIdx.z;           // batch

    // ---- stage A: px-major bf16 hi/lo planes, 16 channels = 32B per px ----
    // staged px p (0..129) <-> global col x0 - 1 + p, rows r-1..r+1
    for (int p = tid; p < 130; p += 128) {
        const int gx = x0 - 1 + p;
        const bool xv = ((unsigned)gx < (unsigned)Ws);
        #pragma unroll
        for (int kh = 0; kh < 3; kh++) {
            const int gy = r - 1 + kh;
            const bool v = xv && ((unsigned)gy < (unsigned)Hs);
            const float* src = x + (((size_t)b * Cs) * Hs + gy) * Ws + gx;

            float val[16];
            #pragma unroll
            for (int c = 0; c < 16; c++)
                val[c] = v ? src[(size_t)c * Hs * Ws] : 0.f;

            __nv_bfloat16 hb[16], lb[16];
            #pragma unroll
            for (int c = 0; c < 16; c++) {
                hb[c] = __float2bfloat16(val[c]);
                lb[c] = __float2bfloat16(val[c] - __bfloat162float(hb[c]));
            }
            const int off = (kh * PITCH + p) * 32;
            uint4 q;
            q.x = pk2(hb[0],hb[1]);   q.y = pk2(hb[2],hb[3]);
            q.z = pk2(hb[4],hb[5]);   q.w = pk2(hb[6],hb[7]);
            *reinterpret_cast<uint4*>(smem + off) = q;
            q.x = pk2(hb[8],hb[9]);   q.y = pk2(hb[10],hb[11]);
            q.z = pk2(hb[12],hb[13]); q.w = pk2(hb[14],hb[15]);
            *reinterpret_cast<uint4*>(smem + off + 16) = q;
            q.x = pk2(lb[0],lb[1]);   q.y = pk2(lb[2],lb[3]);
            q.z = pk2(lb[4],lb[5]);   q.w = pk2(lb[6],lb[7]);
            *reinterpret_cast<uint4*>(smem + APLANE + off) = q;
            q.x = pk2(lb[8],lb[9]);   q.y = pk2(lb[10],lb[11]);
            q.z = pk2(lb[12],lb[13]); q.w = pk2(lb[14],lb[15]);
            *reinterpret_cast<uint4*>(smem + APLANE + off + 16) = q;
        }
    }

    // ---- stage B: [plane][tap][n 32][k 16 bf16 = 32B] ----
    // weights src layout: [(c*9 + tap)*32 + n]
    for (int i = tid; i < 9 * 32; i += 128) {
        const int tap = i >> 5;
        const int n   = i & 31;
        float val[16];
        #pragma unroll
        for (int c = 0; c < 16; c++)
            val[c] = weights[(c * 9 + tap) * Fs + n];

        __nv_bfloat16 hb[16], lb[16];
        #pragma unroll
        for (int c = 0; c < 16; c++) {
            hb[c] = __float2bfloat16(val[c]);
            lb[c] = __float2bfloat16(val[c] - __bfloat162float(hb[c]));
        }
        const int off = 2 * APLANE + (tap * 32 + n) * 32;
        uint4 q;
        q.x = pk2(hb[0],hb[1]);   q.y = pk2(hb[2],hb[3]);
        q.z = pk2(hb[4],hb[5]);   q.w = pk2(hb[6],hb[7]);
        *reinterpret_cast<uint4*>(smem + off) = q;
        q.x = pk2(hb[8],hb[9]);   q.y = pk2(hb[10],hb[11]);
        q.z = pk2(hb[12],hb[13]); q.w = pk2(hb[14],hb[15]);
        *reinterpret_cast<uint4*>(smem + off + 16) = q;
        q.x = pk2(lb[0],lb[1]);   q.y = pk2(lb[2],lb[3]);
        q.z = pk2(lb[4],lb[5]);   q.w = pk2(lb[6],lb[7]);
        *reinterpret_cast<uint4*>(smem + BPLANE + off) = q;
        q.x = pk2(lb[8],lb[9]);   q.y = pk2(lb[10],lb[11]);
        q.z = pk2(lb[12],lb[13]); q.w = pk2(lb[14],lb[15]);
        *reinterpret_cast<uint4*>(smem + BPLANE + off + 16) = q;
    }
    __syncthreads();

    // ---- main loop: 3 precision terms x 9 taps, K=16 each ----
    const int px0    = warp * 32;
    const int g      = lane >> 2;       // group id
    const int tig    = lane & 3;        // thread in group
    const uint32_t a_sel  = (lane & 15);
    const uint32_t a_hi16 = (lane >> 4) * 16;

    float acc[2][4][4];
    #pragma unroll
    for (int mt = 0; mt < 2; mt++)
        #pragma unroll
        for (int jn = 0; jn < 4; jn++)
            #pragma unroll
            for (int k = 0; k < 4; k++) acc[mt][jn][k] = 0.f;

    #pragma unroll
    for (int term = 0; term < 3; term++) {
        const uint32_t aB = sb + ((term == 2) ? APLANE : 0);              // Al only term2
        const uint32_t bB = sb + 2 * APLANE + ((term == 1) ? BPLANE : 0); // Bl only term1
        #pragma unroll
        for (int tap = 0; tap < 9; tap++) {
            const int kh = tap / 3, kw = tap % 3;
            // A fragments (two m16 tiles)
            const uint32_t arow =
                aB + (kh * PITCH + px0 + kw + a_sel) * 32 + a_hi16;
            uint32_t afr[2][4];
            ldmA(arow,       afr[0]);
            ldmA(arow + 512, afr[1]);   // +16 px

            const char* bptr = smem + (bB - sb) + tap * 1024 + g * 32 + 4 * tig;
            #pragma unroll
            for (int jn = 0; jn < 4; jn++) {
                const uint32_t b0 = *reinterpret_cast<const uint32_t*>(bptr + jn * 256);
                const uint32_t b1 = *reinterpret_cast<const uint32_t*>(bptr + jn * 256 + 16);
                mma16816(acc[0][jn], afr[0], b0, b1);
                mma16816(acc[1][jn], afr[1], b0, b1);
            }
        }
    }

    // ---- epilogue: bias + sigmoid + store ----
    // D frag: d0:(px=g, f=2*tig) d1:(px=g, f=2*tig+1) d2:(px=g+8,...) d3
    #pragma unroll
    for (int mt = 0; mt < 2; mt++) {
        const int pxa = x0 + px0 + mt * 16 + g;
        const int pxb = pxa + 8;
        #pragma unroll
        for (int jn = 0; jn < 4; jn++) {
            const int f0 = jn * 8 + 2 * tig;
            const int f1 = f0 + 1;
            const float* d = acc[mt][jn];

            const size_t bi0 = ((size_t)f0 * Hs + r) * Ws;
            const size_t bi1 = ((size_t)f1 * Hs + r) * Ws;
            const size_t oi0 = (((size_t)b * Fs + f0) * Hs + r) * Ws;
            const size_t oi1 = (((size_t)b * Fs + f1) * Hs + r) * Ws;

            float v0 = d[0] + biases[bi0 + pxa];
            float v1 = d[1] + biases[bi1 + pxa];
            float v2 = d[2] + biases[bi0 + pxb];
            float v3 = d[3] + biases[bi1 + pxb];

            out[oi0 + pxa] = 1.f / (1.f + __expf(-v0));
            out[oi1 + pxa] = 1.f / (1.f + __expf(-v1));
            out[oi0 + pxb] = 1.f / (1.f + __expf(-v2));
            out[oi1 + pxb] = 1.f / (1.f + __expf(-v3));
        }
    }
}

extern "C" void kernel_launch(void* const* d_in, const int* in_sizes, int n_in,
                              void* d_out, int out_size) {
    const float* x       = (const float*)d_in[0];
    const float* weights = (const float*)d_in[1];
    const float* biases  = (const float*)d_in[2];
    float* out = (float*)d_out;

    dim3 grid(Ws / MPX, Hs, Bs);   // (2, 256, 16) = 8192 blocks
    dim3 block(128);
    conv_hmma_kernel<<<grid, block>>>(x, weights, biases, out);
}

// round 9
// speedup vs baseline: 2.8071x; 1.2212x over previous
#include <cuda_runtime.h>
#include <cuda_bf16.h>
#include <stdint.h>

// ---------------- problem constants ----------------
#define Bs 16
#define Cs 16
#define Hs 256
#define Ws 256
#define Fs 32

#define MPX 128                 // output px per block (half an image row)
#define PITCH 132               // staged px slots per kh row (130 used)
#define APLANE (3 * PITCH * 32) // bytes per A precision plane (32B/px) = 12672
#define BPLANE (9 * 32 * 32)    // bytes per B precision plane = 9216
#define SMEM_SZ (2 * APLANE + 2 * BPLANE)   // 43776 B

__device__ __forceinline__ uint32_t smem_u32(const void* p) {
    uint32_t a;
    asm("{ .reg .u64 t; cvta.to.shared.u64 t, %1; cvt.u32.u64 %0, t; }"
        : "=r"(a) : "l"(p));
    return a;
}
__device__ __forceinline__ uint32_t pk2(__nv_bfloat16 a, __nv_bfloat16 b) {
    union { __nv_bfloat162 v; uint32_t u; } cv;
    cv.v = __nv_bfloat162(a, b);   // low half = a (even index)
    return cv.u;
}
__device__ __forceinline__ void ldm4(uint32_t addr, uint32_t* a) {
    asm volatile("ldmatrix.sync.aligned.m8n8.x4.shared.b16 {%0,%1,%2,%3}, [%4];"
                 : "=r"(a[0]), "=r"(a[1]), "=r"(a[2]), "=r"(a[3]) : "r"(addr));
}
__device__ __forceinline__ void mma16816(float* d, const uint32_t* a,
                                         uint32_t b0, uint32_t b1) {
    asm volatile(
        "mma.sync.aligned.m16n8k16.row.col.f32.bf16.bf16.f32 "
        "{%0,%1,%2,%3}, {%4,%5,%6,%7}, {%8,%9}, {%0,%1,%2,%3};"
        : "+f"(d[0]), "+f"(d[1]), "+f"(d[2]), "+f"(d[3])
        : "r"(a[0]), "r"(a[1]), "r"(a[2]), "r"(a[3]), "r"(b0), "r"(b1));
}

__global__ __launch_bounds__(128, 4)
void conv_hmma_kernel(const float* __restrict__ x,
                      const float* __restrict__ weights,
                      const float* __restrict__ biases,
                      float* __restrict__ out) {
    __shared__ __align__(128) char smem[SMEM_SZ];
    const uint32_t sb = smem_u32(smem);

    const int tid  = threadIdx.x;
    const int warp = tid >> 5;
    const int lane = tid & 31;

    const int x0 = blockIdx.x * MPX;     // 0 or 128
    const int r  = blockIdx.y;           // output row
    const int b  = blockIdx.z;           // batch

    // ---- stage A: px-major bf16 hi/lo planes, 16 channels = 32B per px ----
    for (int p = tid; p < 130; p += 128) {
        const int gx = x0 - 1 + p;
        const bool xv = ((unsigned)gx < (unsigned)Ws);
        #pragma unroll
        for (int kh = 0; kh < 3; kh++) {
            const int gy = r - 1 + kh;
            const bool v = xv && ((unsigned)gy < (unsigned)Hs);
            const float* src = x + (((size_t)b * Cs) * Hs + gy) * Ws + gx;

            float val[16];
            #pragma unroll
            for (int c = 0; c < 16; c++)
                val[c] = v ? src[(size_t)c * Hs * Ws] : 0.f;

            __nv_bfloat16 hb[16], lb[16];
            #pragma unroll
            for (int c = 0; c < 16; c++) {
                hb[c] = __float2bfloat16(val[c]);
                lb[c] = __float2bfloat16(val[c] - __bfloat162float(hb[c]));
            }
            const int off = (kh * PITCH + p) * 32;
            uint4 q;
            q.x = pk2(hb[0],hb[1]);   q.y = pk2(hb[2],hb[3]);
            q.z = pk2(hb[4],hb[5]);   q.w = pk2(hb[6],hb[7]);
            *reinterpret_cast<uint4*>(smem + off) = q;
            q.x = pk2(hb[8],hb[9]);   q.y = pk2(hb[10],hb[11]);
            q.z = pk2(hb[12],hb[13]); q.w = pk2(hb[14],hb[15]);
            *reinterpret_cast<uint4*>(smem + off + 16) = q;
            q.x = pk2(lb[0],lb[1]);   q.y = pk2(lb[2],lb[3]);
            q.z = pk2(lb[4],lb[5]);   q.w = pk2(lb[6],lb[7]);
            *reinterpret_cast<uint4*>(smem + APLANE + off) = q;
            q.x = pk2(lb[8],lb[9]);   q.y = pk2(lb[10],lb[11]);
            q.z = pk2(lb[12],lb[13]); q.w = pk2(lb[14],lb[15]);
            *reinterpret_cast<uint4*>(smem + APLANE + off + 16) = q;
        }
    }

    // ---- stage B: [plane][tap][n 32][k 16 bf16 = 32B] ----
    for (int i = tid; i < 9 * 32; i += 128) {
        const int tap = i >> 5;
        const int n   = i & 31;
        float val[16];
        #pragma unroll
        for (int c = 0; c < 16; c++)
            val[c] = weights[(c * 9 + tap) * Fs + n];

        __nv_bfloat16 hb[16], lb[16];
        #pragma unroll
        for (int c = 0; c < 16; c++) {
            hb[c] = __float2bfloat16(val[c]);
            lb[c] = __float2bfloat16(val[c] - __bfloat162float(hb[c]));
        }
        const int off = 2 * APLANE + (tap * 32 + n) * 32;
        uint4 q;
        q.x = pk2(hb[0],hb[1]);   q.y = pk2(hb[2],hb[3]);
        q.z = pk2(hb[4],hb[5]);   q.w = pk2(hb[6],hb[7]);
        *reinterpret_cast<uint4*>(smem + off) = q;
        q.x = pk2(hb[8],hb[9]);   q.y = pk2(hb[10],hb[11]);
        q.z = pk2(hb[12],hb[13]); q.w = pk2(hb[14],hb[15]);
        *reinterpret_cast<uint4*>(smem + off + 16) = q;
        q.x = pk2(lb[0],lb[1]);   q.y = pk2(lb[2],lb[3]);
        q.z = pk2(lb[4],lb[5]);   q.w = pk2(lb[6],lb[7]);
        *reinterpret_cast<uint4*>(smem + BPLANE + off) = q;
        q.x = pk2(lb[8],lb[9]);   q.y = pk2(lb[10],lb[11]);
        q.z = pk2(lb[12],lb[13]); q.w = pk2(lb[14],lb[15]);
        *reinterpret_cast<uint4*>(smem + BPLANE + off + 16) = q;
    }
    __syncthreads();

    // ---- main loop: 9 taps, all 3 precision terms fused per tap ----
    const int px0    = warp * 32;
    const uint32_t a_sel  = (lane & 15);
    const uint32_t a_hi16 = (lane >> 4) * 16;
    // B ldmatrix lane addressing: matrix m = lane>>3 ↔ (jn = m>>1, khalf = m&1)
    const uint32_t b_lane_off =
        ((uint32_t)((lane >> 4)) * 256) + (uint32_t)(lane & 7) * 32 +
        ((uint32_t)((lane >> 3) & 1)) * 16;

    float acc[2][4][4];
    #pragma unroll
    for (int mt = 0; mt < 2; mt++)
        #pragma unroll
        for (int jn = 0; jn < 4; jn++)
            #pragma unroll
            for (int k = 0; k < 4; k++) acc[mt][jn][k] = 0.f;

    #pragma unroll
    for (int tap = 0; tap < 9; tap++) {
        const int kh = tap / 3, kw = tap % 3;

        // A fragments: hi & lo planes, two m16 tiles each
        const uint32_t arow = sb + (kh * PITCH + px0 + kw + a_sel) * 32 + a_hi16;
        uint32_t ah[2][4], al[2][4];
        ldm4(arow,                ah[0]);
        ldm4(arow + 512,          ah[1]);
        ldm4(arow + APLANE,       al[0]);
        ldm4(arow + APLANE + 512, al[1]);

        // B fragments via ldmatrix: [jn0,b0][jn0,b1][jn1,b0][jn1,b1] per x4
        const uint32_t bbase = sb + 2 * APLANE + tap * 1024 + b_lane_off;
        uint32_t bh[8], bl[8];
        ldm4(bbase,                  bh);       // jn 0,1 (hi)
        ldm4(bbase + 512,            bh + 4);   // jn 2,3 (hi)
        ldm4(bbase + BPLANE,         bl);       // jn 0,1 (lo)
        ldm4(bbase + BPLANE + 512,   bl + 4);   // jn 2,3 (lo)

        #pragma unroll
        for (int jn = 0; jn < 4; jn++) {
            const uint32_t h0 = bh[2 * jn], h1 = bh[2 * jn + 1];
            const uint32_t l0 = bl[2 * jn], l1 = bl[2 * jn + 1];
            mma16816(acc[0][jn], ah[0], h0, h1);   // Ah*Bh
            mma16816(acc[1][jn], ah[1], h0, h1);
            mma16816(acc[0][jn], al[0], h0, h1);   // Al*Bh
            mma16816(acc[1][jn], al[1], h0, h1);
            mma16816(acc[0][jn], ah[0], l0, l1);   // Ah*Bl
            mma16816(acc[1][jn], ah[1], l0, l1);
        }
    }

    // ---- epilogue: bias + sigmoid + store ----
    const int g   = lane >> 2;
    const int tig = lane & 3;
    #pragma unroll
    for (int mt = 0; mt < 2; mt++) {
        const int pxa = x0 + px0 + mt * 16 + g;
        const int pxb = pxa + 8;
        #pragma unroll
        for (int jn = 0; jn < 4; jn++) {
            const int f0 = jn * 8 + 2 * tig;
            const int f1 = f0 + 1;
            const float* d = acc[mt][jn];

            const size_t bi0 = ((size_t)f0 * Hs + r) * Ws;
            const size_t bi1 = ((size_t)f1 * Hs + r) * Ws;
            const size_t oi0 = (((size_t)b * Fs + f0) * Hs + r) * Ws;
            const size_t oi1 = (((size_t)b * Fs + f1) * Hs + r) * Ws;

            float v0 = d[0] + biases[bi0 + pxa];
            float v1 = d[1] + biases[bi1 + pxa];
            float v2 = d[2] + biases[bi0 + pxb];
            float v3 = d[3] + biases[bi1 + pxb];

            out[oi0 + pxa] = 1.f / (1.f + __expf(-v0));
            out[oi1 + pxa] = 1.f / (1.f + __expf(-v1));
            out[oi0 + pxb] = 1.f / (1.f + __expf(-v2));
            out[oi1 + pxb] = 1.f / (1.f + __expf(-v3));
        }
    }
}

extern "C" void kernel_launch(void* const* d_in, const int* in_sizes, int n_in,
                              void* d_out, int out_size) {
    const float* x       = (const float*)d_in[0];
    const float* weights = (const float*)d_in[1];
    const float* biases  = (const float*)d_in[2];
    float* out = (float*)d_out;

    dim3 grid(Ws / MPX, Hs, Bs);   // (2, 256, 16) = 8192 blocks
    dim3 block(128);
    conv_hmma_kernel<<<grid, block>>>(x, weights, biases, out);
}

// round 10
// speedup vs baseline: 3.3106x; 1.1793x over previous
#include <cuda_runtime.h>
#include <cuda_bf16.h>
#include <stdint.h>

// ---------------- problem constants ----------------
#define Bs 16
#define Cs 16
#define Hs 256
#define Ws 256
#define Fs 32

#define MPX 128                 // output px per block (half an image row)
#define PITCH 132               // staged px slots per kh row (130 used)
// A: 4 planes [prec(hi,lo)][khalf(c0-7,c8-15)], 16B per px row
#define APL (3 * PITCH * 16)    // bytes per A plane = 6336
// B: 4 planes [prec][khalf], rows = 16B per n
#define BOFF (4 * APL)          // 25344
#define BPL (9 * 32 * 16)       // bytes per B plane = 4608
#define SMEM_SZ (BOFF + 4 * BPL)   // 43776 B

__device__ __forceinline__ uint32_t smem_u32(const void* p) {
    uint32_t a;
    asm("{ .reg .u64 t; cvta.to.shared.u64 t, %1; cvt.u32.u64 %0, t; }"
        : "=r"(a) : "l"(p));
    return a;
}
__device__ __forceinline__ uint32_t pk2(__nv_bfloat16 a, __nv_bfloat16 b) {
    union { __nv_bfloat162 v; uint32_t u; } cv;
    cv.v = __nv_bfloat162(a, b);   // low half = a (even index)
    return cv.u;
}
__device__ __forceinline__ void ldm4(uint32_t addr, uint32_t* a) {
    asm volatile("ldmatrix.sync.aligned.m8n8.x4.shared.b16 {%0,%1,%2,%3}, [%4];"
                 : "=r"(a[0]), "=r"(a[1]), "=r"(a[2]), "=r"(a[3]) : "r"(addr));
}
__device__ __forceinline__ void mma16816(float* d, const uint32_t* a,
                                         uint32_t b0, uint32_t b1) {
    asm volatile(
        "mma.sync.aligned.m16n8k16.row.col.f32.bf16.bf16.f32 "
        "{%0,%1,%2,%3}, {%4,%5,%6,%7}, {%8,%9}, {%0,%1,%2,%3};"
        : "+f"(d[0]), "+f"(d[1]), "+f"(d[2]), "+f"(d[3])
        : "r"(a[0]), "r"(a[1]), "r"(a[2]), "r"(a[3]), "r"(b0), "r"(b1));
}

__global__ __launch_bounds__(128, 4)
void conv_hmma_kernel(const float* __restrict__ x,
                      const float* __restrict__ weights,
                      const float* __restrict__ biases,
                      float* __restrict__ out) {
    __shared__ __align__(128) char smem[SMEM_SZ];
    const uint32_t sb = smem_u32(smem);

    const int tid  = threadIdx.x;
    const int warp = tid >> 5;
    const int lane = tid & 31;

    const int x0 = blockIdx.x * MPX;     // 0 or 128
    const int r  = blockIdx.y;           // output row
    const int b  = blockIdx.z;           // batch

    // ---- stage A: px-major bf16, planes [hi-k0][hi-k1][lo-k0][lo-k1], 16B rows ----
    for (int p = tid; p < 130; p += 128) {
        const int gx = x0 - 1 + p;
        const bool xv = ((unsigned)gx < (unsigned)Ws);
        #pragma unroll
        for (int kh = 0; kh < 3; kh++) {
            const int gy = r - 1 + kh;
            const bool v = xv && ((unsigned)gy < (unsigned)Hs);
            const float* src = x + (((size_t)b * Cs) * Hs + gy) * Ws + gx;

            float val[16];
            #pragma unroll
            for (int c = 0; c < 16; c++)
                val[c] = v ? src[(size_t)c * Hs * Ws] : 0.f;

            __nv_bfloat16 hb[16], lb[16];
            #pragma unroll
            for (int c = 0; c < 16; c++) {
                hb[c] = __float2bfloat16(val[c]);
                lb[c] = __float2bfloat16(val[c] - __bfloat162float(hb[c]));
            }
            const int off = (kh * PITCH + p) * 16;
            uint4 q;
            q.x = pk2(hb[0],hb[1]);   q.y = pk2(hb[2],hb[3]);
            q.z = pk2(hb[4],hb[5]);   q.w = pk2(hb[6],hb[7]);
            *reinterpret_cast<uint4*>(smem + 0 * APL + off) = q;   // hi k0-7
            q.x = pk2(hb[8],hb[9]);   q.y = pk2(hb[10],hb[11]);
            q.z = pk2(hb[12],hb[13]); q.w = pk2(hb[14],hb[15]);
            *reinterpret_cast<uint4*>(smem + 1 * APL + off) = q;   // hi k8-15
            q.x = pk2(lb[0],lb[1]);   q.y = pk2(lb[2],lb[3]);
            q.z = pk2(lb[4],lb[5]);   q.w = pk2(lb[6],lb[7]);
            *reinterpret_cast<uint4*>(smem + 2 * APL + off) = q;   // lo k0-7
            q.x = pk2(lb[8],lb[9]);   q.y = pk2(lb[10],lb[11]);
            q.z = pk2(lb[12],lb[13]); q.w = pk2(lb[14],lb[15]);
            *reinterpret_cast<uint4*>(smem + 3 * APL + off) = q;   // lo k8-15
        }
    }

    // ---- stage B: planes [hi-k0][hi-k1][lo-k0][lo-k1], row = 16B per (tap,n) ----
    for (int i = tid; i < 9 * 32; i += 128) {
        const int tap = i >> 5;
        const int n   = i & 31;
        float val[16];
        #pragma unroll
        for (int c = 0; c < 16; c++)
            val[c] = weights[(c * 9 + tap) * Fs + n];

        __nv_bfloat16 hb[16], lb[16];
        #pragma unroll
        for (int c = 0; c < 16; c++) {
            hb[c] = __float2bfloat16(val[c]);
            lb[c] = __float2bfloat16(val[c] - __bfloat162float(hb[c]));
        }
        const int off = BOFF + i * 16;
        uint4 q;
        q.x = pk2(hb[0],hb[1]);   q.y = pk2(hb[2],hb[3]);
        q.z = pk2(hb[4],hb[5]);   q.w = pk2(hb[6],hb[7]);
        *reinterpret_cast<uint4*>(smem + 0 * BPL + off) = q;
        q.x = pk2(hb[8],hb[9]);   q.y = pk2(hb[10],hb[11]);
        q.z = pk2(hb[12],hb[13]); q.w = pk2(hb[14],hb[15]);
        *reinterpret_cast<uint4*>(smem + 1 * BPL + off) = q;
        q.x = pk2(lb[0],lb[1]);   q.y = pk2(lb[2],lb[3]);
        q.z = pk2(lb[4],lb[5]);   q.w = pk2(lb[6],lb[7]);
        *reinterpret_cast<uint4*>(smem + 2 * BPL + off) = q;
        q.x = pk2(lb[8],lb[9]);   q.y = pk2(lb[10],lb[11]);
        q.z = pk2(lb[12],lb[13]); q.w = pk2(lb[14],lb[15]);
        *reinterpret_cast<uint4*>(smem + 3 * BPL + off) = q;
    }
    __syncthreads();

    // ---- main loop: 9 taps, 3 precision terms fused per tap ----
    const int px0 = warp * 32;
    // A ldmatrix: lanes 0-15 -> khalf0 plane (matrices 0,1: px tiles, k0-7),
    //             lanes 16-31 -> khalf1 plane (matrices 2,3: k8-15)
    const uint32_t a_plane = (uint32_t)(lane >> 4) * APL;
    const uint32_t a_sel   = (uint32_t)(lane & 15);
    // B ldmatrix: m0=lanes0-7 (jn0,k0-7) m1=lanes8-15 (jn0,k8-15)
    //             m2=lanes16-23 (jn1,k0-7) m3=lanes24-31 (jn1,k8-15)
    const uint32_t b_lane_off =
        ((uint32_t)((lane >> 3) & 1)) * BPL +       // khalf plane
        ((uint32_t)(lane >> 4)) * 128 +             // jn within pair (8 n-rows)
        (uint32_t)(lane & 7) * 16;                  // n row

    float acc[2][4][4];
    #pragma unroll
    for (int mt = 0; mt < 2; mt++)
        #pragma unroll
        for (int jn = 0; jn < 4; jn++)
            #pragma unroll
            for (int k = 0; k < 4; k++) acc[mt][jn][k] = 0.f;

    #pragma unroll
    for (int tap = 0; tap < 9; tap++) {
        const int kh = tap / 3, kw = tap % 3;

        // A fragments: hi & lo planes, two m16 tiles each (tile2 = +16 px = +256B)
        const uint32_t arow = sb + a_plane + (kh * PITCH + px0 + kw + a_sel) * 16;
        uint32_t ah[2][4], al[2][4];
        ldm4(arow,                 ah[0]);
        ldm4(arow + 256,           ah[1]);
        ldm4(arow + 2 * APL,       al[0]);
        ldm4(arow + 2 * APL + 256, al[1]);

        // B fragments: x4 -> {jn0.b0, jn0.b1, jn1.b0, jn1.b1}; +256B -> jn2,jn3
        const uint32_t bbase = sb + BOFF + tap * 512 + b_lane_off;
        uint32_t bh[8], bl[8];
        ldm4(bbase,                 bh);       // jn 0,1 (hi)
        ldm4(bbase + 256,           bh + 4);   // jn 2,3 (hi)
        ldm4(bbase + 2 * BPL,       bl);       // jn 0,1 (lo)
        ldm4(bbase + 2 * BPL + 256, bl + 4);   // jn 2,3 (lo)

        #pragma unroll
        for (int jn = 0; jn < 4; jn++) {
            const uint32_t h0 = bh[2 * jn], h1 = bh[2 * jn + 1];
            const uint32_t l0 = bl[2 * jn], l1 = bl[2 * jn + 1];
            mma16816(acc[0][jn], ah[0], h0, h1);   // Ah*Bh
            mma16816(acc[1][jn], ah[1], h0, h1);
            mma16816(acc[0][jn], al[0], h0, h1);   // Al*Bh
            mma16816(acc[1][jn], al[1], h0, h1);
            mma16816(acc[0][jn], ah[0], l0, l1);   // Ah*Bl
            mma16816(acc[1][jn], ah[1], l0, l1);
        }
    }

    // ---- epilogue: bias + sigmoid + store ----
    const int g   = lane >> 2;
    const int tig = lane & 3;
    #pragma unroll
    for (int mt = 0; mt < 2; mt++) {
        const int pxa = x0 + px0 + mt * 16 + g;
        const int pxb = pxa + 8;
        #pragma unroll
        for (int jn = 0; jn < 4; jn++) {
            const int f0 = jn * 8 + 2 * tig;
            const int f1 = f0 + 1;
            const float* d = acc[mt][jn];

            const size_t bi0 = ((size_t)f0 * Hs + r) * Ws;
            const size_t bi1 = ((size_t)f1 * Hs + r) * Ws;
            const size_t oi0 = (((size_t)b * Fs + f0) * Hs + r) * Ws;
            const size_t oi1 = (((size_t)b * Fs + f1) * Hs + r) * Ws;

            float v0 = d[0] + biases[bi0 + pxa];
            float v1 = d[1] + biases[bi1 + pxa];
            float v2 = d[2] + biases[bi0 + pxb];
            float v3 = d[3] + biases[bi1 + pxb];

            out[oi0 + pxa] = 1.f / (1.f + __expf(-v0));
            out[oi1 + pxa] = 1.f / (1.f + __expf(-v1));
            out[oi0 + pxb] = 1.f / (1.f + __expf(-v2));
            out[oi1 + pxb] = 1.f / (1.f + __expf(-v3));
        }
    }
}

extern "C" void kernel_launch(void* const* d_in, const int* in_sizes, int n_in,
                              void* d_out, int out_size) {
    const float* x       = (const float*)d_in[0];
    const float* weights = (const float*)d_in[1];
    const float* biases  = (const float*)d_in[2];
    float* out = (float*)d_out;

    dim3 grid(Ws / MPX, Hs, Bs);   // (2, 256, 16) = 8192 blocks
    dim3 block(128);
    conv_hmma_kernel<<<grid, block>>>(x, weights, biases, out);
}